// round 1
// baseline (speedup 1.0000x reference)
#include <cuda_runtime.h>
#include <math_constants.h>

#define NNK      16
#define TILE     2048
#define THREADS  128

// Global accumulators (double for order-insensitive accuracy under atomics).
__device__ double g_sum_minrow;
__device__ double g_sum_mincol;
__device__ double g_sum_dens;

__global__ void init_kernel() {
    g_sum_minrow = 0.0;
    g_sum_mincol = 0.0;
    g_sum_dens   = 0.0;
}

// Insert d2 into sorted-ascending knn[NNK] (dropping the old max).
// Caller guarantees d2 < knn[NNK-1].
__device__ __forceinline__ void topk_insert(float (&knn)[NNK], float d2) {
    float x = d2;
#pragma unroll
    for (int k = 0; k < NNK; k++) {
        float lo = fminf(knn[k], x);
        x        = fmaxf(knn[k], x);
        knn[k]   = lo;
    }
}

// Scan one candidate cloud (N points, layout [N,3]) maintaining top-NNK
// smallest squared distances (matmul form, matches reference math).
__device__ __forceinline__ void scan_topk(const float* __restrict__ src, int N,
                                          float qx, float qy, float qz, float x2,
                                          float (&knn)[NNK], float4* tile) {
    for (int t0 = 0; t0 < N; t0 += TILE) {
        int cnt = min(TILE, N - t0);
        __syncthreads();
        for (int j = threadIdx.x; j < cnt; j += THREADS) {
            const float* s = src + (size_t)(t0 + j) * 3;
            float a = s[0], b = s[1], c = s[2];
            tile[j] = make_float4(a, b, c, a * a + b * b + c * c);
        }
        __syncthreads();
        float kmax = knn[NNK - 1];
#pragma unroll 4
        for (int j = 0; j < cnt; j++) {
            float4 s  = tile[j];
            float  d2 = fmaf(qx, s.x, fmaf(qy, s.y, fmaf(qz, s.z, x2 + s.w)));
            if (d2 < kmax) {
                topk_insert(knn, d2);
                kmax = knn[NNK - 1];
            }
        }
    }
}

// Kernel A: one thread per TRUE point i.
//  - top-16 sq-dists to y_pred  -> minrow (slot 0) + knndis
//  - top-16 sq-dists to y_true  -> knndis2 (includes self ~0)
//  - accumulate sum(minrow) and sum |sqrt(knnp)-sqrt(knnt)|
__global__ void __launch_bounds__(THREADS)
knn_kernel(const float* __restrict__ y_pred, const float* __restrict__ y_true, int N) {
    __shared__ float4 tile[TILE];
    __shared__ float  redA[THREADS / 32];
    __shared__ float  redB[THREADS / 32];

    int b = blockIdx.y;
    int i = blockIdx.x * THREADS + threadIdx.x;

    const float* yt = y_true + (size_t)b * N * 3;
    const float* yp = y_pred + (size_t)b * N * 3;

    float px = yt[(size_t)i * 3 + 0];
    float py = yt[(size_t)i * 3 + 1];
    float pz = yt[(size_t)i * 3 + 2];
    float x2 = px * px + py * py + pz * pz;
    float qx = -2.f * px, qy = -2.f * py, qz = -2.f * pz;

    float knnp[NNK], knnt[NNK];
#pragma unroll
    for (int k = 0; k < NNK; k++) { knnp[k] = CUDART_INF_F; knnt[k] = CUDART_INF_F; }

    scan_topk(yp, N, qx, qy, qz, x2, knnp, tile);
    scan_topk(yt, N, qx, qy, qz, x2, knnt, tile);

    float minr = sqrtf(fmaxf(knnp[0], 0.f));
    float dens = 0.f;
#pragma unroll
    for (int k = 0; k < NNK; k++) {
        float dp = sqrtf(fmaxf(knnp[k], 0.f));
        float dt = sqrtf(fmaxf(knnt[k], 0.f));
        dens += fabsf(dp - dt);
    }

    // block reduce (two values at once)
#pragma unroll
    for (int o = 16; o > 0; o >>= 1) {
        minr += __shfl_down_sync(0xffffffffu, minr, o);
        dens += __shfl_down_sync(0xffffffffu, dens, o);
    }
    if ((threadIdx.x & 31) == 0) {
        redA[threadIdx.x >> 5] = minr;
        redB[threadIdx.x >> 5] = dens;
    }
    __syncthreads();
    if (threadIdx.x == 0) {
        float a = 0.f, c = 0.f;
#pragma unroll
        for (int w = 0; w < THREADS / 32; w++) { a += redA[w]; c += redB[w]; }
        atomicAdd(&g_sum_minrow, (double)a);
        atomicAdd(&g_sum_dens,   (double)c);
    }
}

// Kernel B: one thread per PRED point j; min sq-dist to y_true -> mincol.
__global__ void __launch_bounds__(THREADS)
mincol_kernel(const float* __restrict__ y_pred, const float* __restrict__ y_true, int N) {
    __shared__ float4 tile[TILE];
    __shared__ float  redA[THREADS / 32];

    int b = blockIdx.y;
    int j = blockIdx.x * THREADS + threadIdx.x;

    const float* yt = y_true + (size_t)b * N * 3;
    const float* yp = y_pred + (size_t)b * N * 3;

    float px = yp[(size_t)j * 3 + 0];
    float py = yp[(size_t)j * 3 + 1];
    float pz = yp[(size_t)j * 3 + 2];
    float x2 = px * px + py * py + pz * pz;
    float qx = -2.f * px, qy = -2.f * py, qz = -2.f * pz;

    float m = CUDART_INF_F;
    for (int t0 = 0; t0 < N; t0 += TILE) {
        int cnt = min(TILE, N - t0);
        __syncthreads();
        for (int jj = threadIdx.x; jj < cnt; jj += THREADS) {
            const float* s = yt + (size_t)(t0 + jj) * 3;
            float a = s[0], bb = s[1], c = s[2];
            tile[jj] = make_float4(a, bb, c, a * a + bb * bb + c * c);
        }
        __syncthreads();
#pragma unroll 8
        for (int jj = 0; jj < cnt; jj++) {
            float4 s  = tile[jj];
            float  d2 = fmaf(qx, s.x, fmaf(qy, s.y, fmaf(qz, s.z, x2 + s.w)));
            m = fminf(m, d2);
        }
    }

    float mc = sqrtf(fmaxf(m, 0.f));
#pragma unroll
    for (int o = 16; o > 0; o >>= 1) mc += __shfl_down_sync(0xffffffffu, mc, o);
    if ((threadIdx.x & 31) == 0) redA[threadIdx.x >> 5] = mc;
    __syncthreads();
    if (threadIdx.x == 0) {
        float a = 0.f;
#pragma unroll
        for (int w = 0; w < THREADS / 32; w++) a += redA[w];
        atomicAdd(&g_sum_mincol, (double)a);
    }
}

__global__ void finalize_kernel(float* __restrict__ out, int BN) {
    double inv   = 1.0 / (double)BN;
    double shape = 0.5 * (g_sum_minrow * inv + g_sum_mincol * inv);
    double dens  = g_sum_dens / ((double)BN * (double)NNK);
    out[0] = (float)(shape + dens);  // data_loss
    out[1] = (float)shape;           // shape_loss
    out[2] = (float)dens;            // density_loss
}

extern "C" void kernel_launch(void* const* d_in, const int* in_sizes, int n_in,
                              void* d_out, int out_size) {
    const float* y_pred = (const float*)d_in[0];
    const float* y_true = (const float*)d_in[1];
    const int B = 2, C = 3;
    int N = in_sizes[0] / (B * C);

    init_kernel<<<1, 1>>>();
    dim3 grid(N / THREADS, B);
    knn_kernel<<<grid, THREADS>>>(y_pred, y_true, N);
    mincol_kernel<<<grid, THREADS>>>(y_pred, y_true, N);
    finalize_kernel<<<1, 1>>>((float*)d_out, B * N);
}